// round 5
// baseline (speedup 1.0000x reference)
#include <cuda_runtime.h>
#include <cuda_bf16.h>
#include <cstdint>
#include <cstring>

// Problem constants
#define B_   2
#define C_   64
#define H_   192
#define W_   192
#define HW_  (H_*W_)          // 36864
#define KK_  9
#define HP_  194
#define WP_  194
#define HPWP_ (HP_*WP_)       // 37636
#define CI_  65               // C+1
#define OC_  18               // 2*KK

// Scratch (device globals)
__device__ float    g_xp  [B_*HPWP_*C_];     // padded x, NHWC  (~19.3 MB)
__device__ float    g_off [B_*OC_*HW_];      // offsets (~5.3 MB)
__device__ uint16_t g_wtbh[KK_*C_*C_];       // weight hi bf16, [kk][oc][c]
__device__ uint16_t g_wtbl[KK_*C_*C_];       // weight lo bf16

// ---------------------------------------------------------------------------
// helpers
// ---------------------------------------------------------------------------
__device__ __forceinline__ uint32_t cvt_bf16x2(float hi, float lo) {
    uint32_t r;
    asm("cvt.rn.satfinite.bf16x2.f32 %0, %1, %2;" : "=r"(r) : "f"(hi), "f"(lo));
    return r;
}

__device__ __forceinline__ void mma16816(float& d0, float& d1, float& d2, float& d3,
                                         uint32_t a0, uint32_t a1, uint32_t a2, uint32_t a3,
                                         uint32_t b0, uint32_t b1) {
    asm volatile("mma.sync.aligned.m16n8k16.row.col.f32.bf16.bf16.f32 "
                 "{%0,%1,%2,%3},{%4,%5,%6,%7},{%8,%9},{%0,%1,%2,%3};"
                 : "+f"(d0), "+f"(d1), "+f"(d2), "+f"(d3)
                 : "r"(a0), "r"(a1), "r"(a2), "r"(a3), "r"(b0), "r"(b1));
}

// ---------------------------------------------------------------------------
// Kernel 1a: zero g_xp
// ---------------------------------------------------------------------------
__global__ void zero_xp_kernel() {
    int i = blockIdx.x * blockDim.x + threadIdx.x;
    if (i < B_*HPWP_*C_/4)
        reinterpret_cast<float4*>(g_xp)[i] = make_float4(0.f, 0.f, 0.f, 0.f);
}

// ---------------------------------------------------------------------------
// Kernel 1b: NCHW -> padded NHWC transpose (interior)
// ---------------------------------------------------------------------------
__global__ __launch_bounds__(256) void nhwc_kernel(const float* __restrict__ x) {
    __shared__ float tile[C_][33];
    const int tid = threadIdx.x;
    const int b   = blockIdx.y;
    const int pix0 = blockIdx.x * 32;

    {
        int ty = tid >> 5, tx = tid & 31;
        #pragma unroll
        for (int c0 = 0; c0 < C_; c0 += 8)
            tile[c0 + ty][tx] = x[((size_t)b * C_ + c0 + ty) * HW_ + pix0 + tx];
    }
    __syncthreads();
    {
        int pi = tid >> 6, c = tid & 63;
        #pragma unroll
        for (int j = 0; j < 8; ++j) {
            int pix = pix0 + j * 4 + pi;
            int ph = pix / W_ + 1, pw = pix % W_ + 1;
            g_xp[((size_t)b * HPWP_ + ph * WP_ + pw) * C_ + c] = tile[c][j * 4 + pi];
        }
    }
}

// ---------------------------------------------------------------------------
// Kernel 2: weight -> bf16 hi/lo, layout [kk][oc][c]
// ---------------------------------------------------------------------------
__global__ void wprep_kernel(const float* __restrict__ w) {
    int i = blockIdx.x * blockDim.x + threadIdx.x;
    if (i >= KK_*C_*C_) return;
    int kk = i / (C_*C_);
    int oc = (i >> 6) & 63;
    int c  = i & 63;
    float v = w[oc * 576 + c * KK_ + kk];
    __nv_bfloat16 h = __float2bfloat16(v);
    float hf = __bfloat162float(h);
    __nv_bfloat16 l = __float2bfloat16(v - hf);
    uint16_t hb, lb;
    memcpy(&hb, &h, 2); memcpy(&lb, &l, 2);
    g_wtbh[(kk * C_ + oc) * C_ + c] = hb;
    g_wtbl[(kk * C_ + oc) * C_ + c] = lb;
}

// ---------------------------------------------------------------------------
// Kernel 3: offset-predicting conv. 128 threads, 1 pixel/thread,
// grid = HW/128 x B = 576 blocks (4 blocks/SM -> latency hidden).
// ---------------------------------------------------------------------------
__global__ __launch_bounds__(128) void offconv_kernel(
    const float* __restrict__ x, const float* __restrict__ depth,
    const float* __restrict__ w_off, const float* __restrict__ bias)
{
    __shared__ float w_s[OC_*CI_*KK_];   // 42.1 KB
    const int tid = threadIdx.x;
    const int b   = blockIdx.y;

    for (int i = tid; i < OC_*CI_*KK_; i += 128) w_s[i] = w_off[i];
    __syncthreads();

    const int p = blockIdx.x * 128 + tid;
    const int oh = p / W_, ow = p % W_;

    int ti[KK_];
    #pragma unroll
    for (int t = 0; t < KK_; ++t) {
        int ih = oh + t / 3 - 1, iw = ow + t % 3 - 1;
        ti[t] = (ih >= 0 && ih < H_ && iw >= 0 && iw < W_) ? ih * W_ + iw : -1;
    }

    float acc[OC_];
    #pragma unroll
    for (int o = 0; o < OC_; ++o) acc[o] = bias[o];

    for (int c = 0; c < CI_; ++c) {
        const float* plane = (c < C_) ? (x + ((size_t)b * C_ + c) * HW_)
                                      : (depth + (size_t)b * HW_);
        float v[KK_];
        #pragma unroll
        for (int t = 0; t < KK_; ++t)
            v[t] = (ti[t] >= 0) ? plane[ti[t]] : 0.f;
        #pragma unroll
        for (int o = 0; o < OC_; ++o) {
            const float* wp = &w_s[(o * CI_ + c) * KK_];
            #pragma unroll
            for (int t = 0; t < KK_; ++t)
                acc[o] = fmaf(v[t], wp[t], acc[o]);
        }
    }

    #pragma unroll
    for (int o = 0; o < OC_; ++o)
        g_off[((size_t)b * OC_ + o) * HW_ + p] = acc[o];
}

// ---------------------------------------------------------------------------
// Kernel 4: fused bilinear gather + mma.sync bf16 GEMM (3-term hi/lo split).
// Block: 64 pixels (M) x 64 out-channels (N), 128 threads (4 warps).
// Warp tile: 32 px x 32 oc. K = 576 as 9 kk-chunks of 64 channels.
// ---------------------------------------------------------------------------
#define APITCH_ 72

__global__ __launch_bounds__(128) void fused_mma_kernel(float* __restrict__ out)
{
    __shared__ __align__(16) uint16_t Ahi[64 * APITCH_];   // 9216 B
    __shared__ __align__(16) uint16_t Alo[64 * APITCH_];   // 9216 B
    __shared__ int    tap_idx[64];
    __shared__ float2 tap_a  [64];

    const int tid  = threadIdx.x;
    const int wid  = tid >> 5;
    const int lane = tid & 31;
    const int b    = blockIdx.y;
    const int pix0 = blockIdx.x * 64;

    const int pxg = wid & 1;    // 0/1: pixel group (32 px)
    const int ocg = wid >> 1;   // 0/1: oc group (32 oc)

    float acc[2][4][4];
    #pragma unroll
    for (int mi = 0; mi < 2; ++mi)
        #pragma unroll
        for (int ni = 0; ni < 4; ++ni)
            #pragma unroll
            for (int r = 0; r < 4; ++r) acc[mi][ni][r] = 0.f;

    const float* xb = g_xp + (size_t)b * HPWP_ * C_;
    const int cg = tid & 15;    // channel group (4 ch)
    const int pb = tid >> 4;    // 0..7

    for (int kk = 0; kk < KK_; ++kk) {
        __syncthreads();   // A smem free (prev mma fragment loads complete)

        // --- taps for this kk (64 pixels) ---
        if (tid < 64) {
            int pix = pix0 + tid;
            int oh = pix / W_, ow = pix % W_;
            float ox = g_off[((size_t)b * OC_ + kk) * HW_ + pix];
            float oy = g_off[((size_t)b * OC_ + KK_ + kk) * HW_ + pix];
            float cx = (float)(oh + kk / 3) + ox;
            float cy = (float)(ow + kk % 3) + oy;
            cx = fminf(fmaxf(cx, 0.f), (float)(HP_ - 1));
            cy = fminf(fmaxf(cy, 0.f), (float)(WP_ - 1));
            int tlx = (int)floorf(cx); tlx = min(max(tlx, 0), HP_ - 2);
            int tly = (int)floorf(cy); tly = min(max(tly, 0), WP_ - 2);
            tap_idx[tid] = tlx * WP_ + tly;
            tap_a[tid] = make_float2(cx - (float)tlx, cy - (float)tly);
        }
        __syncthreads();

        // --- gather: 64 px x 64 ch -> Ahi/Alo bf16 tiles ---
        #pragma unroll 2
        for (int i = 0; i < 8; ++i) {
            int p = pb + 8 * i;
            int idx = tap_idx[p];
            float2 a = tap_a[p];
            const float4* q = reinterpret_cast<const float4*>(xb + (size_t)idx * C_) + cg;
            float4 x00 = q[0];
            float4 x01 = q[16];           // +1 col (NHWC: +64 floats)
            float4 x10 = q[WP_ * 16];     // +1 row
            float4 x11 = q[(WP_ + 1) * 16];
            float4 v;
            {
                float r0, r1;
                r0 = fmaf(a.y, x01.x - x00.x, x00.x);
                r1 = fmaf(a.y, x11.x - x10.x, x10.x);
                v.x = fmaf(a.x, r1 - r0, r0);
                r0 = fmaf(a.y, x01.y - x00.y, x00.y);
                r1 = fmaf(a.y, x11.y - x10.y, x10.y);
                v.y = fmaf(a.x, r1 - r0, r0);
                r0 = fmaf(a.y, x01.z - x00.z, x00.z);
                r1 = fmaf(a.y, x11.z - x10.z, x10.z);
                v.z = fmaf(a.x, r1 - r0, r0);
                r0 = fmaf(a.y, x01.w - x00.w, x00.w);
                r1 = fmaf(a.y, x11.w - x10.w, x10.w);
                v.w = fmaf(a.x, r1 - r0, r0);
            }
            uint32_t h01 = cvt_bf16x2(v.y, v.x);   // lo16=v.x, hi16=v.y
            uint32_t h23 = cvt_bf16x2(v.w, v.z);
            float l0 = v.x - __uint_as_float(h01 << 16);
            float l1 = v.y - __uint_as_float(h01 & 0xFFFF0000u);
            float l2 = v.z - __uint_as_float(h23 << 16);
            float l3 = v.w - __uint_as_float(h23 & 0xFFFF0000u);
            uint32_t q01 = cvt_bf16x2(l1, l0);
            uint32_t q23 = cvt_bf16x2(l3, l2);
            int eo = p * APITCH_ + cg * 4;
            *reinterpret_cast<uint2*>(&Ahi[eo]) = make_uint2(h01, h23);
            *reinterpret_cast<uint2*>(&Alo[eo]) = make_uint2(q01, q23);
        }
        __syncthreads();

        // --- mma: warp tile 32px x 32oc, K=64 ---
        const uint16_t* wh = g_wtbh + kk * (C_*C_);
        const uint16_t* wl = g_wtbl + kk * (C_*C_);
        const int arow = pxg * 32 + (lane >> 2);      // + mi*16 (+8 for a1/a3)
        const int akol = (lane & 3) * 2;              // + ki*16 (+8 for a2/a3)
        const int brow = ocg * 32 + (lane >> 2);      // + ni*8

        #pragma unroll
        for (int ki = 0; ki < 4; ++ki) {
            const int k0 = ki * 16 + akol;
            uint32_t ah[2][4], al[2][4];
            #pragma unroll
            for (int mi = 0; mi < 2; ++mi) {
                int r0 = (arow + mi * 16) * APITCH_ + k0;
                int r1 = r0 + 8 * APITCH_;
                ah[mi][0] = *reinterpret_cast<const uint32_t*>(&Ahi[r0]);
                ah[mi][1] = *reinterpret_cast<const uint32_t*>(&Ahi[r1]);
                ah[mi][2] = *reinterpret_cast<const uint32_t*>(&Ahi[r0 + 8]);
                ah[mi][3] = *reinterpret_cast<const uint32_t*>(&Ahi[r1 + 8]);
                al[mi][0] = *reinterpret_cast<const uint32_t*>(&Alo[r0]);
                al[mi][1] = *reinterpret_cast<const uint32_t*>(&Alo[r1]);
                al[mi][2] = *reinterpret_cast<const uint32_t*>(&Alo[r0 + 8]);
                al[mi][3] = *reinterpret_cast<const uint32_t*>(&Alo[r1 + 8]);
            }
            #pragma unroll
            for (int ni = 0; ni < 4; ++ni) {
                int boff = (brow + ni * 8) * C_ + k0;
                uint32_t bh0 = *reinterpret_cast<const uint32_t*>(wh + boff);
                uint32_t bh1 = *reinterpret_cast<const uint32_t*>(wh + boff + 8);
                uint32_t bl0 = *reinterpret_cast<const uint32_t*>(wl + boff);
                uint32_t bl1 = *reinterpret_cast<const uint32_t*>(wl + boff + 8);
                #pragma unroll
                for (int mi = 0; mi < 2; ++mi) {
                    float* d = acc[mi][ni];
                    mma16816(d[0], d[1], d[2], d[3],
                             ah[mi][0], ah[mi][1], ah[mi][2], ah[mi][3], bh0, bh1);
                    mma16816(d[0], d[1], d[2], d[3],
                             al[mi][0], al[mi][1], al[mi][2], al[mi][3], bh0, bh1);
                    mma16816(d[0], d[1], d[2], d[3],
                             ah[mi][0], ah[mi][1], ah[mi][2], ah[mi][3], bl0, bl1);
                }
            }
        }
    }

    // --- epilogue: D fragment -> out[b][oc][pix] ---
    #pragma unroll
    for (int mi = 0; mi < 2; ++mi) {
        int px = pix0 + pxg * 32 + mi * 16 + (lane >> 2);
        #pragma unroll
        for (int ni = 0; ni < 4; ++ni) {
            int oc = ocg * 32 + ni * 8 + (lane & 3) * 2;
            float* o0 = out + ((size_t)b * C_ + oc) * HW_;
            float* o1 = out + ((size_t)b * C_ + oc + 1) * HW_;
            o0[px]     = acc[mi][ni][0];
            o1[px]     = acc[mi][ni][1];
            o0[px + 8] = acc[mi][ni][2];
            o1[px + 8] = acc[mi][ni][3];
        }
    }
}

// ---------------------------------------------------------------------------
// Launch
// ---------------------------------------------------------------------------
extern "C" void kernel_launch(void* const* d_in, const int* in_sizes, int n_in,
                              void* d_out, int out_size) {
    const float* x      = (const float*)d_in[0];
    const float* depth  = (const float*)d_in[1];
    const float* w_off  = (const float*)d_in[2];
    const float* bias   = (const float*)d_in[3];
    const float* weight = (const float*)d_in[4];
    float* out = (float*)d_out;

    {
        int n = B_*HPWP_*C_/4;
        zero_xp_kernel<<<(n + 255) / 256, 256>>>();
    }
    {
        dim3 grid(HW_ / 32, B_);
        nhwc_kernel<<<grid, 256>>>(x);
    }
    {
        int n = KK_*C_*C_;
        wprep_kernel<<<(n + 255) / 256, 256>>>(weight);
    }
    {
        dim3 grid(HW_ / 128, B_);
        offconv_kernel<<<grid, 128>>>(x, depth, w_off, bias);
    }
    {
        dim3 grid(HW_ / 64, B_);
        fused_mma_kernel<<<grid, 128>>>(out);
    }
}

// round 6
// speedup vs baseline: 1.1561x; 1.1561x over previous
#include <cuda_runtime.h>
#include <cuda_bf16.h>
#include <cstdint>
#include <cstring>

// Problem constants
#define B_   2
#define C_   64
#define H_   192
#define W_   192
#define HW_  (H_*W_)          // 36864
#define KK_  9
#define HP_  194
#define WP_  194
#define HPWP_ (HP_*WP_)       // 37636
#define CI_  65               // C+1
#define OC_  18               // 2*KK
#define OCH_ 9                // oc per block (half)

// Scratch (device globals)
__device__ float    g_xp  [B_*HPWP_*C_];     // padded x, NHWC  (~19.3 MB)
__device__ float    g_off [B_*OC_*HW_];      // offsets (~5.3 MB)
__device__ uint16_t g_wtbh[KK_*C_*C_];       // weight hi bf16, [kk][oc][c]
__device__ uint16_t g_wtbl[KK_*C_*C_];       // weight lo bf16

// ---------------------------------------------------------------------------
// helpers
// ---------------------------------------------------------------------------
__device__ __forceinline__ uint32_t cvt_bf16x2(float hi, float lo) {
    uint32_t r;
    asm("cvt.rn.satfinite.bf16x2.f32 %0, %1, %2;" : "=r"(r) : "f"(hi), "f"(lo));
    return r;
}

__device__ __forceinline__ void mma16816(float& d0, float& d1, float& d2, float& d3,
                                         uint32_t a0, uint32_t a1, uint32_t a2, uint32_t a3,
                                         uint32_t b0, uint32_t b1) {
    asm volatile("mma.sync.aligned.m16n8k16.row.col.f32.bf16.bf16.f32 "
                 "{%0,%1,%2,%3},{%4,%5,%6,%7},{%8,%9},{%0,%1,%2,%3};"
                 : "+f"(d0), "+f"(d1), "+f"(d2), "+f"(d3)
                 : "r"(a0), "r"(a1), "r"(a2), "r"(a3), "r"(b0), "r"(b1));
}

// ---------------------------------------------------------------------------
// Kernel 1a: zero g_xp
// ---------------------------------------------------------------------------
__global__ void zero_xp_kernel() {
    int i = blockIdx.x * blockDim.x + threadIdx.x;
    if (i < B_*HPWP_*C_/4)
        reinterpret_cast<float4*>(g_xp)[i] = make_float4(0.f, 0.f, 0.f, 0.f);
}

// ---------------------------------------------------------------------------
// Kernel 1b: NCHW -> padded NHWC transpose (interior)
// ---------------------------------------------------------------------------
__global__ __launch_bounds__(256) void nhwc_kernel(const float* __restrict__ x) {
    __shared__ float tile[C_][33];
    const int tid = threadIdx.x;
    const int b   = blockIdx.y;
    const int pix0 = blockIdx.x * 32;

    {
        int ty = tid >> 5, tx = tid & 31;
        #pragma unroll
        for (int c0 = 0; c0 < C_; c0 += 8)
            tile[c0 + ty][tx] = x[((size_t)b * C_ + c0 + ty) * HW_ + pix0 + tx];
    }
    __syncthreads();
    {
        int pi = tid >> 6, c = tid & 63;
        #pragma unroll
        for (int j = 0; j < 8; ++j) {
            int pix = pix0 + j * 4 + pi;
            int ph = pix / W_ + 1, pw = pix % W_ + 1;
            g_xp[((size_t)b * HPWP_ + ph * WP_ + pw) * C_ + c] = tile[c][j * 4 + pi];
        }
    }
}

// ---------------------------------------------------------------------------
// Kernel 2: weight -> bf16 hi/lo, layout [kk][oc][c]
// ---------------------------------------------------------------------------
__global__ void wprep_kernel(const float* __restrict__ w) {
    int i = blockIdx.x * blockDim.x + threadIdx.x;
    if (i >= KK_*C_*C_) return;
    int kk = i / (C_*C_);
    int oc = (i >> 6) & 63;
    int c  = i & 63;
    float v = w[oc * 576 + c * KK_ + kk];
    __nv_bfloat16 h = __float2bfloat16(v);
    float hf = __bfloat162float(h);
    __nv_bfloat16 l = __float2bfloat16(v - hf);
    uint16_t hb, lb;
    memcpy(&hb, &h, 2); memcpy(&lb, &l, 2);
    g_wtbh[(kk * C_ + oc) * C_ + c] = hb;
    g_wtbl[(kk * C_ + oc) * C_ + c] = lb;
}

// ---------------------------------------------------------------------------
// Kernel 3: offset-predicting conv.
// 256 threads, 2 pixels/thread (512 px/block), 9 of 18 out channels per block.
// grid = (HW/512, 2 oc-groups, B) = 288 blocks; smem 21 KB.
// ---------------------------------------------------------------------------
__global__ __launch_bounds__(256) void offconv_kernel(
    const float* __restrict__ x, const float* __restrict__ depth,
    const float* __restrict__ w_off, const float* __restrict__ bias)
{
    __shared__ float w_s[OCH_*CI_*KK_];   // 5265 floats, 21.1 KB
    const int tid = threadIdx.x;
    const int ocg = blockIdx.y;           // 0/1
    const int b   = blockIdx.z;
    const int ob  = ocg * OCH_;

    for (int i = tid; i < OCH_*CI_*KK_; i += 256)
        w_s[i] = w_off[ob * (CI_*KK_) + i];
    __syncthreads();

    const int p0 = blockIdx.x * 512 + tid;
    const int p1 = p0 + 256;

    int ti0[KK_], ti1[KK_];
    {
        int oh0 = p0 / W_, ow0 = p0 % W_;
        int oh1 = p1 / W_, ow1 = p1 % W_;
        #pragma unroll
        for (int t = 0; t < KK_; ++t) {
            int ky = t / 3 - 1, kx = t % 3 - 1;
            int ih0 = oh0 + ky, iw0 = ow0 + kx;
            int ih1 = oh1 + ky, iw1 = ow1 + kx;
            ti0[t] = (ih0 >= 0 && ih0 < H_ && iw0 >= 0 && iw0 < W_) ? ih0 * W_ + iw0 : -1;
            ti1[t] = (ih1 >= 0 && ih1 < H_ && iw1 >= 0 && iw1 < W_) ? ih1 * W_ + iw1 : -1;
        }
    }

    float acc0[OCH_], acc1[OCH_];
    #pragma unroll
    for (int o = 0; o < OCH_; ++o) { float bo = bias[ob + o]; acc0[o] = bo; acc1[o] = bo; }

    for (int c = 0; c < CI_; ++c) {
        const float* plane = (c < C_) ? (x + ((size_t)b * C_ + c) * HW_)
                                      : (depth + (size_t)b * HW_);
        float v0[KK_], v1[KK_];
        #pragma unroll
        for (int t = 0; t < KK_; ++t) {
            v0[t] = (ti0[t] >= 0) ? plane[ti0[t]] : 0.f;
            v1[t] = (ti1[t] >= 0) ? plane[ti1[t]] : 0.f;
        }
        #pragma unroll
        for (int o = 0; o < OCH_; ++o) {
            const float* wp = &w_s[(o * CI_ + c) * KK_];
            #pragma unroll
            for (int t = 0; t < KK_; ++t) {
                float w = wp[t];
                acc0[o] = fmaf(v0[t], w, acc0[o]);
                acc1[o] = fmaf(v1[t], w, acc1[o]);
            }
        }
    }

    #pragma unroll
    for (int o = 0; o < OCH_; ++o) {
        g_off[((size_t)b * OC_ + ob + o) * HW_ + p0] = acc0[o];
        g_off[((size_t)b * OC_ + ob + o) * HW_ + p1] = acc1[o];
    }
}

// ---------------------------------------------------------------------------
// Kernel 4: fused bilinear gather + mma.sync bf16 GEMM (3-term hi/lo split).
// Block: 64 pixels (M) x 64 out-channels (N), 128 threads (4 warps).
// Warp tile: 32 px x 32 oc. K = 576 as 9 kk-chunks of 64 channels.
// ---------------------------------------------------------------------------
#define APITCH_ 72

__global__ __launch_bounds__(128) void fused_mma_kernel(float* __restrict__ out)
{
    __shared__ __align__(16) uint16_t Ahi[64 * APITCH_];   // 9216 B
    __shared__ __align__(16) uint16_t Alo[64 * APITCH_];   // 9216 B
    __shared__ int    tap_idx[64];
    __shared__ float2 tap_a  [64];

    const int tid  = threadIdx.x;
    const int wid  = tid >> 5;
    const int lane = tid & 31;
    const int b    = blockIdx.y;
    const int pix0 = blockIdx.x * 64;

    const int pxg = wid & 1;    // 0/1: pixel group (32 px)
    const int ocg = wid >> 1;   // 0/1: oc group (32 oc)

    float acc[2][4][4];
    #pragma unroll
    for (int mi = 0; mi < 2; ++mi)
        #pragma unroll
        for (int ni = 0; ni < 4; ++ni)
            #pragma unroll
            for (int r = 0; r < 4; ++r) acc[mi][ni][r] = 0.f;

    const float* xb = g_xp + (size_t)b * HPWP_ * C_;
    const int cg = tid & 15;    // channel group (4 ch)
    const int pb = tid >> 4;    // 0..7

    for (int kk = 0; kk < KK_; ++kk) {
        __syncthreads();   // A smem free (prev mma fragment loads complete)

        // --- taps for this kk (64 pixels) ---
        if (tid < 64) {
            int pix = pix0 + tid;
            int oh = pix / W_, ow = pix % W_;
            float ox = g_off[((size_t)b * OC_ + kk) * HW_ + pix];
            float oy = g_off[((size_t)b * OC_ + KK_ + kk) * HW_ + pix];
            float cx = (float)(oh + kk / 3) + ox;
            float cy = (float)(ow + kk % 3) + oy;
            cx = fminf(fmaxf(cx, 0.f), (float)(HP_ - 1));
            cy = fminf(fmaxf(cy, 0.f), (float)(WP_ - 1));
            int tlx = (int)floorf(cx); tlx = min(max(tlx, 0), HP_ - 2);
            int tly = (int)floorf(cy); tly = min(max(tly, 0), WP_ - 2);
            tap_idx[tid] = tlx * WP_ + tly;
            tap_a[tid] = make_float2(cx - (float)tlx, cy - (float)tly);
        }
        __syncthreads();

        // --- gather: 64 px x 64 ch -> Ahi/Alo bf16 tiles ---
        #pragma unroll 2
        for (int i = 0; i < 8; ++i) {
            int p = pb + 8 * i;
            int idx = tap_idx[p];
            float2 a = tap_a[p];
            const float4* q = reinterpret_cast<const float4*>(xb + (size_t)idx * C_) + cg;
            float4 x00 = q[0];
            float4 x01 = q[16];           // +1 col (NHWC: +64 floats)
            float4 x10 = q[WP_ * 16];     // +1 row
            float4 x11 = q[(WP_ + 1) * 16];
            float4 v;
            {
                float r0, r1;
                r0 = fmaf(a.y, x01.x - x00.x, x00.x);
                r1 = fmaf(a.y, x11.x - x10.x, x10.x);
                v.x = fmaf(a.x, r1 - r0, r0);
                r0 = fmaf(a.y, x01.y - x00.y, x00.y);
                r1 = fmaf(a.y, x11.y - x10.y, x10.y);
                v.y = fmaf(a.x, r1 - r0, r0);
                r0 = fmaf(a.y, x01.z - x00.z, x00.z);
                r1 = fmaf(a.y, x11.z - x10.z, x10.z);
                v.z = fmaf(a.x, r1 - r0, r0);
                r0 = fmaf(a.y, x01.w - x00.w, x00.w);
                r1 = fmaf(a.y, x11.w - x10.w, x10.w);
                v.w = fmaf(a.x, r1 - r0, r0);
            }
            uint32_t h01 = cvt_bf16x2(v.y, v.x);   // lo16=v.x, hi16=v.y
            uint32_t h23 = cvt_bf16x2(v.w, v.z);
            float l0 = v.x - __uint_as_float(h01 << 16);
            float l1 = v.y - __uint_as_float(h01 & 0xFFFF0000u);
            float l2 = v.z - __uint_as_float(h23 << 16);
            float l3 = v.w - __uint_as_float(h23 & 0xFFFF0000u);
            uint32_t q01 = cvt_bf16x2(l1, l0);
            uint32_t q23 = cvt_bf16x2(l3, l2);
            int eo = p * APITCH_ + cg * 4;
            *reinterpret_cast<uint2*>(&Ahi[eo]) = make_uint2(h01, h23);
            *reinterpret_cast<uint2*>(&Alo[eo]) = make_uint2(q01, q23);
        }
        __syncthreads();

        // --- mma: warp tile 32px x 32oc, K=64 ---
        const uint16_t* wh = g_wtbh + kk * (C_*C_);
        const uint16_t* wl = g_wtbl + kk * (C_*C_);
        const int arow = pxg * 32 + (lane >> 2);      // + mi*16 (+8 for a1/a3)
        const int akol = (lane & 3) * 2;              // + ki*16 (+8 for a2/a3)
        const int brow = ocg * 32 + (lane >> 2);      // + ni*8

        #pragma unroll
        for (int ki = 0; ki < 4; ++ki) {
            const int k0 = ki * 16 + akol;
            uint32_t ah[2][4], al[2][4];
            #pragma unroll
            for (int mi = 0; mi < 2; ++mi) {
                int r0 = (arow + mi * 16) * APITCH_ + k0;
                int r1 = r0 + 8 * APITCH_;
                ah[mi][0] = *reinterpret_cast<const uint32_t*>(&Ahi[r0]);
                ah[mi][1] = *reinterpret_cast<const uint32_t*>(&Ahi[r1]);
                ah[mi][2] = *reinterpret_cast<const uint32_t*>(&Ahi[r0 + 8]);
                ah[mi][3] = *reinterpret_cast<const uint32_t*>(&Ahi[r1 + 8]);
                al[mi][0] = *reinterpret_cast<const uint32_t*>(&Alo[r0]);
                al[mi][1] = *reinterpret_cast<const uint32_t*>(&Alo[r1]);
                al[mi][2] = *reinterpret_cast<const uint32_t*>(&Alo[r0 + 8]);
                al[mi][3] = *reinterpret_cast<const uint32_t*>(&Alo[r1 + 8]);
            }
            #pragma unroll
            for (int ni = 0; ni < 4; ++ni) {
                int boff = (brow + ni * 8) * C_ + k0;
                uint32_t bh0 = *reinterpret_cast<const uint32_t*>(wh + boff);
                uint32_t bh1 = *reinterpret_cast<const uint32_t*>(wh + boff + 8);
                uint32_t bl0 = *reinterpret_cast<const uint32_t*>(wl + boff);
                uint32_t bl1 = *reinterpret_cast<const uint32_t*>(wl + boff + 8);
                #pragma unroll
                for (int mi = 0; mi < 2; ++mi) {
                    float* d = acc[mi][ni];
                    mma16816(d[0], d[1], d[2], d[3],
                             ah[mi][0], ah[mi][1], ah[mi][2], ah[mi][3], bh0, bh1);
                    mma16816(d[0], d[1], d[2], d[3],
                             al[mi][0], al[mi][1], al[mi][2], al[mi][3], bh0, bh1);
                    mma16816(d[0], d[1], d[2], d[3],
                             ah[mi][0], ah[mi][1], ah[mi][2], ah[mi][3], bl0, bl1);
                }
            }
        }
    }

    // --- epilogue: D fragment -> out[b][oc][pix] ---
    #pragma unroll
    for (int mi = 0; mi < 2; ++mi) {
        int px = pix0 + pxg * 32 + mi * 16 + (lane >> 2);
        #pragma unroll
        for (int ni = 0; ni < 4; ++ni) {
            int oc = ocg * 32 + ni * 8 + (lane & 3) * 2;
            float* o0 = out + ((size_t)b * C_ + oc) * HW_;
            float* o1 = out + ((size_t)b * C_ + oc + 1) * HW_;
            o0[px]     = acc[mi][ni][0];
            o1[px]     = acc[mi][ni][1];
            o0[px + 8] = acc[mi][ni][2];
            o1[px + 8] = acc[mi][ni][3];
        }
    }
}

// ---------------------------------------------------------------------------
// Launch
// ---------------------------------------------------------------------------
extern "C" void kernel_launch(void* const* d_in, const int* in_sizes, int n_in,
                              void* d_out, int out_size) {
    const float* x      = (const float*)d_in[0];
    const float* depth  = (const float*)d_in[1];
    const float* w_off  = (const float*)d_in[2];
    const float* bias   = (const float*)d_in[3];
    const float* weight = (const float*)d_in[4];
    float* out = (float*)d_out;

    {
        int n = B_*HPWP_*C_/4;
        zero_xp_kernel<<<(n + 255) / 256, 256>>>();
    }
    {
        dim3 grid(HW_ / 32, B_);
        nhwc_kernel<<<grid, 256>>>(x);
    }
    {
        int n = KK_*C_*C_;
        wprep_kernel<<<(n + 255) / 256, 256>>>(weight);
    }
    {
        dim3 grid(HW_ / 512, 2, B_);
        offconv_kernel<<<grid, 256>>>(x, depth, w_off, bias);
    }
    {
        dim3 grid(HW_ / 64, B_);
        fused_mma_kernel<<<grid, 128>>>(out);
    }
}

// round 7
// speedup vs baseline: 1.3750x; 1.1894x over previous
#include <cuda_runtime.h>
#include <cuda_bf16.h>
#include <cstdint>
#include <cstring>

// Problem constants
#define B_   2
#define C_   64
#define H_   192
#define W_   192
#define HW_  (H_*W_)          // 36864
#define KK_  9
#define HP_  194
#define WP_  194
#define HPWP_ (HP_*WP_)       // 37636
#define CI_  65               // C+1
#define OC_  18               // 2*KK
#define OCH_ 9                // oc per block (half)

// Scratch (device globals)
__device__ float    g_xp  [B_*HPWP_*C_];     // padded x, NHWC  (~19.3 MB)
__device__ float    g_off [B_*OC_*HW_];      // offsets (~5.3 MB)
__device__ uint16_t g_wtbh[KK_*C_*C_];       // weight hi bf16, [kk][oc][c]
__device__ uint16_t g_wtbl[KK_*C_*C_];       // weight lo bf16

// ---------------------------------------------------------------------------
// helpers
// ---------------------------------------------------------------------------
__device__ __forceinline__ uint32_t cvt_bf16x2(float hi, float lo) {
    uint32_t r;
    asm("cvt.rn.satfinite.bf16x2.f32 %0, %1, %2;" : "=r"(r) : "f"(hi), "f"(lo));
    return r;
}

__device__ __forceinline__ void mma16816(float& d0, float& d1, float& d2, float& d3,
                                         uint32_t a0, uint32_t a1, uint32_t a2, uint32_t a3,
                                         uint32_t b0, uint32_t b1) {
    asm volatile("mma.sync.aligned.m16n8k16.row.col.f32.bf16.bf16.f32 "
                 "{%0,%1,%2,%3},{%4,%5,%6,%7},{%8,%9},{%0,%1,%2,%3};"
                 : "+f"(d0), "+f"(d1), "+f"(d2), "+f"(d3)
                 : "r"(a0), "r"(a1), "r"(a2), "r"(a3), "r"(b0), "r"(b1));
}

// ---------------------------------------------------------------------------
// Kernel 1a: zero only the pad border of g_xp (772 px per batch)
// ---------------------------------------------------------------------------
#define NBORD_ (2*WP_ + 2*(HP_-2))   // 772
__global__ void border_kernel() {
    int i = blockIdx.x * blockDim.x + threadIdx.x;
    if (i >= B_ * NBORD_ * 16) return;
    int b   = i / (NBORD_ * 16);
    int r   = i % (NBORD_ * 16);
    int pix = r >> 4;
    int cq  = r & 15;
    int ph, pw;
    if (pix < WP_)            { ph = 0;                pw = pix; }
    else if (pix < 2*WP_)     { ph = HP_ - 1;          pw = pix - WP_; }
    else if (pix < 2*WP_ + (HP_-2)) { ph = pix - 2*WP_ + 1;  pw = 0; }
    else                      { ph = pix - (2*WP_ + (HP_-2)) + 1; pw = WP_ - 1; }
    reinterpret_cast<float4*>(g_xp + ((size_t)b * HPWP_ + ph * WP_ + pw) * C_)[cq] =
        make_float4(0.f, 0.f, 0.f, 0.f);
}

// ---------------------------------------------------------------------------
// Kernel 1b: NCHW -> padded NHWC transpose (interior)
// ---------------------------------------------------------------------------
__global__ __launch_bounds__(256) void nhwc_kernel(const float* __restrict__ x) {
    __shared__ float tile[C_][33];
    const int tid = threadIdx.x;
    const int b   = blockIdx.y;
    const int pix0 = blockIdx.x * 32;

    {
        int ty = tid >> 5, tx = tid & 31;
        #pragma unroll
        for (int c0 = 0; c0 < C_; c0 += 8)
            tile[c0 + ty][tx] = x[((size_t)b * C_ + c0 + ty) * HW_ + pix0 + tx];
    }
    __syncthreads();
    {
        int pi = tid >> 6, c = tid & 63;
        #pragma unroll
        for (int j = 0; j < 8; ++j) {
            int pix = pix0 + j * 4 + pi;
            int ph = pix / W_ + 1, pw = pix % W_ + 1;
            g_xp[((size_t)b * HPWP_ + ph * WP_ + pw) * C_ + c] = tile[c][j * 4 + pi];
        }
    }
}

// ---------------------------------------------------------------------------
// Kernel 2: weight -> bf16 hi/lo, layout [kk][oc][c]
// ---------------------------------------------------------------------------
__global__ void wprep_kernel(const float* __restrict__ w) {
    int i = blockIdx.x * blockDim.x + threadIdx.x;
    if (i >= KK_*C_*C_) return;
    int kk = i / (C_*C_);
    int oc = (i >> 6) & 63;
    int c  = i & 63;
    float v = w[oc * 576 + c * KK_ + kk];
    __nv_bfloat16 h = __float2bfloat16(v);
    float hf = __bfloat162float(h);
    __nv_bfloat16 l = __float2bfloat16(v - hf);
    uint16_t hb, lb;
    memcpy(&hb, &h, 2); memcpy(&lb, &l, 2);
    g_wtbh[(kk * C_ + oc) * C_ + c] = hb;
    g_wtbl[(kk * C_ + oc) * C_ + c] = lb;
}

// ---------------------------------------------------------------------------
// Kernel 3: offset-predicting conv.
// 256 threads, 2 pixels/thread, 9 of 18 oc per block.
// smem weights as [c][tap][12] (9 oc + pad) -> 2xLDS.128+LDS.32 per (c,tap).
// ---------------------------------------------------------------------------
#define WPITCH_ 12
__global__ __launch_bounds__(256) void offconv_kernel(
    const float* __restrict__ x, const float* __restrict__ depth,
    const float* __restrict__ w_off, const float* __restrict__ bias)
{
    __shared__ __align__(16) float w_s[CI_*KK_*WPITCH_];   // 28080 B
    const int tid = threadIdx.x;
    const int ocg = blockIdx.y;           // 0/1
    const int b   = blockIdx.z;
    const int ob  = ocg * OCH_;

    // fill: w_s[(c*9+t)*12 + o] = w_off[(ob+o)*(CI*KK) + c*9 + t]
    for (int i = tid; i < CI_*KK_*OCH_; i += 256) {
        int ct = i / OCH_, o = i % OCH_;
        w_s[ct * WPITCH_ + o] = w_off[(ob + o) * (CI_*KK_) + ct];
    }
    __syncthreads();

    const int p0 = blockIdx.x * 512 + tid;
    const int p1 = p0 + 256;

    int ti0[KK_], ti1[KK_];
    {
        int oh0 = p0 / W_, ow0 = p0 % W_;
        int oh1 = p1 / W_, ow1 = p1 % W_;
        #pragma unroll
        for (int t = 0; t < KK_; ++t) {
            int ky = t / 3 - 1, kx = t % 3 - 1;
            int ih0 = oh0 + ky, iw0 = ow0 + kx;
            int ih1 = oh1 + ky, iw1 = ow1 + kx;
            ti0[t] = (ih0 >= 0 && ih0 < H_ && iw0 >= 0 && iw0 < W_) ? ih0 * W_ + iw0 : -1;
            ti1[t] = (ih1 >= 0 && ih1 < H_ && iw1 >= 0 && iw1 < W_) ? ih1 * W_ + iw1 : -1;
        }
    }

    float acc0[OCH_], acc1[OCH_];
    #pragma unroll
    for (int o = 0; o < OCH_; ++o) { float bo = bias[ob + o]; acc0[o] = bo; acc1[o] = bo; }

    for (int c = 0; c < CI_; ++c) {
        const float* plane = (c < C_) ? (x + ((size_t)b * C_ + c) * HW_)
                                      : (depth + (size_t)b * HW_);
        float v0[KK_], v1[KK_];
        #pragma unroll
        for (int t = 0; t < KK_; ++t) {
            v0[t] = (ti0[t] >= 0) ? plane[ti0[t]] : 0.f;
            v1[t] = (ti1[t] >= 0) ? plane[ti1[t]] : 0.f;
        }
        #pragma unroll
        for (int t = 0; t < KK_; ++t) {
            const float* wp = &w_s[(c * KK_ + t) * WPITCH_];
            float4 wa = *reinterpret_cast<const float4*>(wp);
            float4 wb = *reinterpret_cast<const float4*>(wp + 4);
            float  wc = wp[8];
            acc0[0] = fmaf(v0[t], wa.x, acc0[0]);
            acc0[1] = fmaf(v0[t], wa.y, acc0[1]);
            acc0[2] = fmaf(v0[t], wa.z, acc0[2]);
            acc0[3] = fmaf(v0[t], wa.w, acc0[3]);
            acc0[4] = fmaf(v0[t], wb.x, acc0[4]);
            acc0[5] = fmaf(v0[t], wb.y, acc0[5]);
            acc0[6] = fmaf(v0[t], wb.z, acc0[6]);
            acc0[7] = fmaf(v0[t], wb.w, acc0[7]);
            acc0[8] = fmaf(v0[t], wc,   acc0[8]);
            acc1[0] = fmaf(v1[t], wa.x, acc1[0]);
            acc1[1] = fmaf(v1[t], wa.y, acc1[1]);
            acc1[2] = fmaf(v1[t], wa.z, acc1[2]);
            acc1[3] = fmaf(v1[t], wa.w, acc1[3]);
            acc1[4] = fmaf(v1[t], wb.x, acc1[4]);
            acc1[5] = fmaf(v1[t], wb.y, acc1[5]);
            acc1[6] = fmaf(v1[t], wb.z, acc1[6]);
            acc1[7] = fmaf(v1[t], wb.w, acc1[7]);
            acc1[8] = fmaf(v1[t], wc,   acc1[8]);
        }
    }

    #pragma unroll
    for (int o = 0; o < OCH_; ++o) {
        g_off[((size_t)b * OC_ + ob + o) * HW_ + p0] = acc0[o];
        g_off[((size_t)b * OC_ + ob + o) * HW_ + p1] = acc1[o];
    }
}

// ---------------------------------------------------------------------------
// Kernel 4: fused bilinear gather + mma.sync bf16 GEMM (3-term hi/lo split).
// Block: 64 px x 64 oc, 128 threads. Double-buffered A, all taps precomputed,
// ONE __syncthreads per kk iteration.
// ---------------------------------------------------------------------------
#define APITCH_ 72

struct __align__(8) TapA { float ax, ay; };

__global__ __launch_bounds__(128) void fused_mma_kernel(float* __restrict__ out)
{
    __shared__ __align__(16) uint16_t Ahi[2][64 * APITCH_];   // 2 x 9216 B
    __shared__ __align__(16) uint16_t Alo[2][64 * APITCH_];   // 2 x 9216 B
    __shared__ int  tap_idx[KK_][64];
    __shared__ TapA tap_a  [KK_][64];

    const int tid  = threadIdx.x;
    const int wid  = tid >> 5;
    const int lane = tid & 31;
    const int b    = blockIdx.y;
    const int pix0 = blockIdx.x * 64;

    const int pxg = wid & 1;    // 0/1: pixel group (32 px)
    const int ocg = wid >> 1;   // 0/1: oc group (32 oc)

    float acc[2][4][4];
    #pragma unroll
    for (int mi = 0; mi < 2; ++mi)
        #pragma unroll
        for (int ni = 0; ni < 4; ++ni)
            #pragma unroll
            for (int r = 0; r < 4; ++r) acc[mi][ni][r] = 0.f;

    const float* xb = g_xp + (size_t)b * HPWP_ * C_;
    const int cg = tid & 15;    // channel group (4 ch)
    const int pb = tid >> 4;    // 0..7

    // --- phase 0: all taps (9 kk x 64 px = 576 entries) ---
    for (int e = tid; e < KK_ * 64; e += 128) {
        int kk = e >> 6;
        int p  = e & 63;
        int pix = pix0 + p;
        int oh = pix / W_, ow = pix % W_;
        float ox = g_off[((size_t)b * OC_ + kk) * HW_ + pix];
        float oy = g_off[((size_t)b * OC_ + KK_ + kk) * HW_ + pix];
        float cx = (float)(oh + kk / 3) + ox;
        float cy = (float)(ow + kk % 3) + oy;
        cx = fminf(fmaxf(cx, 0.f), (float)(HP_ - 1));
        cy = fminf(fmaxf(cy, 0.f), (float)(WP_ - 1));
        int tlx = (int)floorf(cx); tlx = min(max(tlx, 0), HP_ - 2);
        int tly = (int)floorf(cy); tly = min(max(tly, 0), WP_ - 2);
        tap_idx[kk][p] = tlx * WP_ + tly;
        tap_a[kk][p].ax = cx - (float)tlx;
        tap_a[kk][p].ay = cy - (float)tly;
    }
    __syncthreads();

    // gather for one kk into buffer buf
    auto gather = [&](int kk, int buf) {
        #pragma unroll 2
        for (int i = 0; i < 8; ++i) {
            int p = pb + 8 * i;
            int idx = tap_idx[kk][p];
            TapA a = tap_a[kk][p];
            const float4* q = reinterpret_cast<const float4*>(xb + (size_t)idx * C_) + cg;
            float4 x00 = q[0];
            float4 x01 = q[16];
            float4 x10 = q[WP_ * 16];
            float4 x11 = q[(WP_ + 1) * 16];
            float4 v;
            {
                float r0, r1;
                r0 = fmaf(a.ay, x01.x - x00.x, x00.x);
                r1 = fmaf(a.ay, x11.x - x10.x, x10.x);
                v.x = fmaf(a.ax, r1 - r0, r0);
                r0 = fmaf(a.ay, x01.y - x00.y, x00.y);
                r1 = fmaf(a.ay, x11.y - x10.y, x10.y);
                v.y = fmaf(a.ax, r1 - r0, r0);
                r0 = fmaf(a.ay, x01.z - x00.z, x00.z);
                r1 = fmaf(a.ay, x11.z - x10.z, x10.z);
                v.z = fmaf(a.ax, r1 - r0, r0);
                r0 = fmaf(a.ay, x01.w - x00.w, x00.w);
                r1 = fmaf(a.ay, x11.w - x10.w, x10.w);
                v.w = fmaf(a.ax, r1 - r0, r0);
            }
            uint32_t h01 = cvt_bf16x2(v.y, v.x);
            uint32_t h23 = cvt_bf16x2(v.w, v.z);
            float l0 = v.x - __uint_as_float(h01 << 16);
            float l1 = v.y - __uint_as_float(h01 & 0xFFFF0000u);
            float l2 = v.z - __uint_as_float(h23 << 16);
            float l3 = v.w - __uint_as_float(h23 & 0xFFFF0000u);
            uint32_t q01 = cvt_bf16x2(l1, l0);
            uint32_t q23 = cvt_bf16x2(l3, l2);
            int eo = p * APITCH_ + cg * 4;
            *reinterpret_cast<uint2*>(&Ahi[buf][eo]) = make_uint2(h01, h23);
            *reinterpret_cast<uint2*>(&Alo[buf][eo]) = make_uint2(q01, q23);
        }
    };

    gather(0, 0);
    __syncthreads();

    const int arow = pxg * 32 + (lane >> 2);
    const int akol = (lane & 3) * 2;
    const int brow = ocg * 32 + (lane >> 2);

    for (int kk = 0; kk < KK_; ++kk) {
        const int buf = kk & 1;
        // --- mma: warp tile 32px x 32oc, K=64 (reads buf) ---
        const uint16_t* wh = g_wtbh + kk * (C_*C_);
        const uint16_t* wl = g_wtbl + kk * (C_*C_);

        #pragma unroll
        for (int ki = 0; ki < 4; ++ki) {
            const int k0 = ki * 16 + akol;
            uint32_t ah[2][4], al[2][4];
            #pragma unroll
            for (int mi = 0; mi < 2; ++mi) {
                int r0 = (arow + mi * 16) * APITCH_ + k0;
                int r1 = r0 + 8 * APITCH_;
                ah[mi][0] = *reinterpret_cast<const uint32_t*>(&Ahi[buf][r0]);
                ah[mi][1] = *reinterpret_cast<const uint32_t*>(&Ahi[buf][r1]);
                ah[mi][2] = *reinterpret_cast<const uint32_t*>(&Ahi[buf][r0 + 8]);
                ah[mi][3] = *reinterpret_cast<const uint32_t*>(&Ahi[buf][r1 + 8]);
                al[mi][0] = *reinterpret_cast<const uint32_t*>(&Alo[buf][r0]);
                al[mi][1] = *reinterpret_cast<const uint32_t*>(&Alo[buf][r1]);
                al[mi][2] = *reinterpret_cast<const uint32_t*>(&Alo[buf][r0 + 8]);
                al[mi][3] = *reinterpret_cast<const uint32_t*>(&Alo[buf][r1 + 8]);
            }
            #pragma unroll
            for (int ni = 0; ni < 4; ++ni) {
                int boff = (brow + ni * 8) * C_ + k0;
                uint32_t bh0 = *reinterpret_cast<const uint32_t*>(wh + boff);
                uint32_t bh1 = *reinterpret_cast<const uint32_t*>(wh + boff + 8);
                uint32_t bl0 = *reinterpret_cast<const uint32_t*>(wl + boff);
                uint32_t bl1 = *reinterpret_cast<const uint32_t*>(wl + boff + 8);
                #pragma unroll
                for (int mi = 0; mi < 2; ++mi) {
                    float* d = acc[mi][ni];
                    mma16816(d[0], d[1], d[2], d[3],
                             ah[mi][0], ah[mi][1], ah[mi][2], ah[mi][3], bh0, bh1);
                    mma16816(d[0], d[1], d[2], d[3],
                             al[mi][0], al[mi][1], al[mi][2], al[mi][3], bh0, bh1);
                    mma16816(d[0], d[1], d[2], d[3],
                             ah[mi][0], ah[mi][1], ah[mi][2], ah[mi][3], bl0, bl1);
                }
            }
        }
        // --- gather next kk into other buffer, then single sync ---
        if (kk + 1 < KK_) gather(kk + 1, buf ^ 1);
        __syncthreads();
    }

    // --- epilogue: D fragment -> out[b][oc][pix] ---
    #pragma unroll
    for (int mi = 0; mi < 2; ++mi) {
        int px = pix0 + pxg * 32 + mi * 16 + (lane >> 2);
        #pragma unroll
        for (int ni = 0; ni < 4; ++ni) {
            int oc = ocg * 32 + ni * 8 + (lane & 3) * 2;
            float* o0 = out + ((size_t)b * C_ + oc) * HW_;
            float* o1 = out + ((size_t)b * C_ + oc + 1) * HW_;
            o0[px]     = acc[mi][ni][0];
            o1[px]     = acc[mi][ni][1];
            o0[px + 8] = acc[mi][ni][2];
            o1[px + 8] = acc[mi][ni][3];
        }
    }
}

// ---------------------------------------------------------------------------
// Launch
// ---------------------------------------------------------------------------
extern "C" void kernel_launch(void* const* d_in, const int* in_sizes, int n_in,
                              void* d_out, int out_size) {
    const float* x      = (const float*)d_in[0];
    const float* depth  = (const float*)d_in[1];
    const float* w_off  = (const float*)d_in[2];
    const float* bias   = (const float*)d_in[3];
    const float* weight = (const float*)d_in[4];
    float* out = (float*)d_out;

    {
        int n = B_ * NBORD_ * 16;
        border_kernel<<<(n + 255) / 256, 256>>>();
    }
    {
        dim3 grid(HW_ / 32, B_);
        nhwc_kernel<<<grid, 256>>>(x);
    }
    {
        int n = KK_*C_*C_;
        wprep_kernel<<<(n + 255) / 256, 256>>>(weight);
    }
    {
        dim3 grid(HW_ / 512, 2, B_);
        offconv_kernel<<<grid, 256>>>(x, depth, w_off, bias);
    }
    {
        dim3 grid(HW_ / 64, B_);
        fused_mma_kernel<<<grid, 128>>>(out);
    }
}